// round 9
// baseline (speedup 1.0000x reference)
#include <cuda_runtime.h>
#include <cuda_bf16.h>
#include <math.h>
#include <stdint.h>

// Problem constants
#define S 128
#define B 32
#define E 300
#define H 200
#define G 800      // 4*H
#define NT 1600    // 2 dirs * G
#define MROWS 4096 // S*B
#define T 17

// Scratch (device globals). Wt*/X0/H0 hold tf32-converted bit patterns
// (stored as float bit-casts); GI*/H1 are true fp32.
__device__ float g_Wt0[300 * NT];
__device__ float g_Wt1[400 * NT];
__device__ float g_X0[MROWS * E];
__device__ float g_GI0[MROWS * NT];
__device__ float g_GI1[MROWS * NT];
__device__ float g_H0[MROWS * 400];
__device__ float g_H1[MROWS * 400];

__device__ __forceinline__ float sigf(float x) { return 1.0f / (1.0f + expf(-x)); }

__device__ __forceinline__ float ex2f(float x) {
    float y; asm("ex2.approx.f32 %0, %1;" : "=f"(y) : "f"(x)); return y;
}
__device__ __forceinline__ float rcpf(float x) {
    float y; asm("rcp.approx.f32 %0, %1;" : "=f"(y) : "f"(x)); return y;
}
__device__ __forceinline__ float fsig(float x) {   // 1/(1+e^-x)
    return rcpf(1.0f + ex2f(-1.4426950408889634f * x));
}
__device__ __forceinline__ float ftanh(float x) {  // 1 - 2/(1+e^{2x})
    return 1.0f - 2.0f * rcpf(1.0f + ex2f(2.8853901617779268f * x));
}

__device__ __forceinline__ uint32_t smem_u32(const void* p) {
    uint32_t a;
    asm("{ .reg .u64 t; cvta.to.shared.u64 t, %1; cvt.u32.u64 %0, t; }" : "=r"(a) : "l"(p));
    return a;
}
__device__ __forceinline__ void st_cluster_f32(uint32_t laddr, uint32_t rank, float v) {
    uint32_t ra;
    asm volatile("mapa.shared::cluster.u32 %0, %1, %2;" : "=r"(ra) : "r"(laddr), "r"(rank));
    asm volatile("st.shared::cluster.f32 [%0], %1;" :: "r"(ra), "f"(v) : "memory");
}
#define CL_ARRIVE() asm volatile("barrier.cluster.arrive.aligned;" ::: "memory")
#define CL_WAIT()   asm volatile("barrier.cluster.wait.aligned;" ::: "memory")

__device__ __forceinline__ uint32_t f2tf32(float f) {
    uint32_t u;
    asm("cvt.rna.tf32.f32 %0, %1;" : "=r"(u) : "f"(f));
    return u;
}
__device__ __forceinline__ uint64_t fma2(uint64_t a, uint64_t b, uint64_t c) {
    uint64_t d;
    asm("fma.rn.f32x2 %0, %1, %2, %3;" : "=l"(d) : "l"(a), "l"(b), "l"(c));
    return d;
}
__device__ __forceinline__ float2 unpack2(uint64_t v) {
    uint32_t lo, hi;
    asm("mov.b64 {%0,%1}, %2;" : "=r"(lo), "=r"(hi) : "l"(v));
    return make_float2(__uint_as_float(lo), __uint_as_float(hi));
}
__device__ __forceinline__ void mma_tf32(float* c, const uint32_t* a, const uint32_t* b) {
    asm volatile(
        "mma.sync.aligned.m16n8k8.row.col.f32.tf32.tf32.f32 "
        "{%0,%1,%2,%3}, {%4,%5,%6,%7}, {%8,%9}, {%0,%1,%2,%3};"
        : "+f"(c[0]), "+f"(c[1]), "+f"(c[2]), "+f"(c[3])
        : "r"(a[0]), "r"(a[1]), "r"(a[2]), "r"(a[3]), "r"(b[0]), "r"(b[1]));
}

// ---------------------------------------------------------------------------
// Fused prep
// ---------------------------------------------------------------------------
__global__ void prep(const float* __restrict__ Wih0, const float* __restrict__ Wih1,
                     const int* __restrict__ words, const float* __restrict__ emb) {
    const int task = blockIdx.y;
    const int idx = blockIdx.x * 256 + threadIdx.x;
    if (task == 0) {
        if (idx < NT * 300) {
            int n = idx / 300, k = idx - n * 300;
            g_Wt0[k * NT + n] = __uint_as_float(f2tf32(Wih0[idx]));
        }
    } else if (task == 1) {
        if (idx < NT * 400) {
            int n = idx / 400, k = idx - n * 400;
            g_Wt1[k * NT + n] = __uint_as_float(f2tf32(Wih1[idx]));
        }
    } else {
        if (idx < MROWS * 75) {
            int m = idx / 75, c4 = idx - m * 75;
            int s = m >> 5, b = m & 31;
            int w = words[b * S + s];
            float4 v = ((const float4*)(emb + (long long)w * E))[c4];
            float4 o;
            o.x = __uint_as_float(f2tf32(v.x));
            o.y = __uint_as_float(f2tf32(v.y));
            o.z = __uint_as_float(f2tf32(v.z));
            o.w = __uint_as_float(f2tf32(v.w));
            ((float4*)g_X0)[idx] = o;
        }
    }
}

// ---------------------------------------------------------------------------
// tf32 tensor-core GEMM (unchanged from R8)
// ---------------------------------------------------------------------------
#define ASZ (128 * 20)
#define BSZ (16 * 72)
__global__ void __launch_bounds__(256) gemm_tc(const float* __restrict__ bias,
                                               int K, int layer) {
    const uint32_t* A  = (const uint32_t*)(layer ? g_H0  : g_X0);
    const uint32_t* Bm = (const uint32_t*)(layer ? g_Wt1 : g_Wt0);
    float* C           = layer ? g_GI1 : g_GI0;
    __shared__ uint32_t sm[2][ASZ + BSZ];

    const int tid = threadIdx.x;
    const int lane = tid & 31, wid = tid >> 5;
    const int g = lane >> 2, tg = lane & 3;
    const int warp_m = (wid & 3) * 32;
    const int warp_n = (wid >> 2) * 32;
    const int m0 = blockIdx.y * 128, n0 = blockIdx.x * 64;

    float acc[2][4][4] = {};
    const int ntiles = (K + 15) / 16;
    const int br = tid >> 4, bc4 = tid & 15;

    uint4 la[2], lb;
#pragma unroll
    for (int i = 0; i < 2; i++) {
        int idx = tid + i * 256;
        int r = idx >> 2, c4 = idx & 3;
        int kk = c4 * 4;
        uint4 v = make_uint4(0u, 0u, 0u, 0u);
        if (kk + 3 < K) v = *(const uint4*)&A[(m0 + r) * K + kk];
        else {
            if (kk + 0 < K) v.x = A[(m0 + r) * K + kk + 0];
            if (kk + 1 < K) v.y = A[(m0 + r) * K + kk + 1];
            if (kk + 2 < K) v.z = A[(m0 + r) * K + kk + 2];
            if (kk + 3 < K) v.w = A[(m0 + r) * K + kk + 3];
        }
        la[i] = v;
    }
    {
        lb = make_uint4(0u, 0u, 0u, 0u);
        if (br < K) lb = *(const uint4*)&Bm[br * NT + n0 + bc4 * 4];
    }
#pragma unroll
    for (int i = 0; i < 2; i++) {
        int idx = tid + i * 256;
        int r = idx >> 2, c4 = idx & 3;
        *(uint4*)&sm[0][r * 20 + c4 * 4] = la[i];
    }
    *(uint4*)&sm[0][ASZ + br * 72 + bc4 * 4] = lb;
    __syncthreads();

    int cur = 0;
    for (int t = 0; t < ntiles; t++) {
        if (t + 1 < ntiles) {
            const int k0 = (t + 1) * 16;
#pragma unroll
            for (int i = 0; i < 2; i++) {
                int idx = tid + i * 256;
                int r = idx >> 2, c4 = idx & 3;
                int kk = k0 + c4 * 4;
                uint4 v = make_uint4(0u, 0u, 0u, 0u);
                if (kk + 3 < K) v = *(const uint4*)&A[(m0 + r) * K + kk];
                else {
                    if (kk + 0 < K) v.x = A[(m0 + r) * K + kk + 0];
                    if (kk + 1 < K) v.y = A[(m0 + r) * K + kk + 1];
                    if (kk + 2 < K) v.z = A[(m0 + r) * K + kk + 2];
                    if (kk + 3 < K) v.w = A[(m0 + r) * K + kk + 3];
                }
                la[i] = v;
            }
            int kk = k0 + br;
            lb = make_uint4(0u, 0u, 0u, 0u);
            if (kk < K) lb = *(const uint4*)&Bm[kk * NT + n0 + bc4 * 4];
        }
        const uint32_t* As = sm[cur];
        const uint32_t* Bs = sm[cur] + ASZ;
#pragma unroll
        for (int k8 = 0; k8 < 16; k8 += 8) {
            uint32_t a[2][4], b[4][2];
#pragma unroll
            for (int mi = 0; mi < 2; mi++) {
                int row = warp_m + mi * 16;
                a[mi][0] = As[(row + g) * 20 + k8 + tg];
                a[mi][1] = As[(row + g + 8) * 20 + k8 + tg];
                a[mi][2] = As[(row + g) * 20 + k8 + tg + 4];
                a[mi][3] = As[(row + g + 8) * 20 + k8 + tg + 4];
            }
#pragma unroll
            for (int ni = 0; ni < 4; ni++) {
                int col = warp_n + ni * 8 + g;
                b[ni][0] = Bs[(k8 + tg) * 72 + col];
                b[ni][1] = Bs[(k8 + tg + 4) * 72 + col];
            }
#pragma unroll
            for (int mi = 0; mi < 2; mi++)
#pragma unroll
                for (int ni = 0; ni < 4; ni++)
                    mma_tf32(acc[mi][ni], a[mi], b[ni]);
        }
        if (t + 1 < ntiles) {
            uint32_t* d = sm[cur ^ 1];
#pragma unroll
            for (int i = 0; i < 2; i++) {
                int idx = tid + i * 256;
                int r = idx >> 2, c4 = idx & 3;
                *(uint4*)&d[r * 20 + c4 * 4] = la[i];
            }
            *(uint4*)&d[ASZ + br * 72 + bc4 * 4] = lb;
        }
        __syncthreads();
        cur ^= 1;
    }

#pragma unroll
    for (int mi = 0; mi < 2; mi++) {
        int r0 = m0 + warp_m + mi * 16 + g;
        int r1 = r0 + 8;
#pragma unroll
        for (int ni = 0; ni < 4; ni++) {
            int c = n0 + warp_n + ni * 8 + tg * 2;
            float2 bv = *(const float2*)&bias[c];
            float2 o0, o1;
            o0.x = acc[mi][ni][0] + bv.x; o0.y = acc[mi][ni][1] + bv.y;
            o1.x = acc[mi][ni][2] + bv.x; o1.y = acc[mi][ni][3] + bv.y;
            *(float2*)&C[(size_t)r0 * NT + c] = o0;
            *(float2*)&C[(size_t)r1 * NT + c] = o1;
        }
    }
}

// ---------------------------------------------------------------------------
// Cluster-resident LSTM recurrence, rank-templated.
// Ownership per rank: j-slices {52,48,52,48} so each CTA's own k-slice is
// ulonglong2-aligned. Per step: local k-quarter computed between cluster
// arrive and wait (hides UCGABAR wait); remote 3/4 after wait. Fast-math
// gates (ex2/rcp.approx). h double-buffered; 1 arrive + 1 wait per step.
// ---------------------------------------------------------------------------
#define KQ_BODY(kq) {                                   \
    ulonglong2 h0 = hp0[kq];                            \
    ulonglong2 h1 = hp1[kq];                            \
    a00 = fma2(upair[2 * (kq)],     h0.x, a00);         \
    a01 = fma2(upair[2 * (kq) + 1], h0.y, a01);         \
    a10 = fma2(upair[2 * (kq)],     h1.x, a10);         \
    a11 = fma2(upair[2 * (kq) + 1], h1.y, a11); }

template <int CR>
__device__ __forceinline__ void lstm_body(const float* __restrict__ GI,
                                          const float* __restrict__ WhhD,
                                          float* __restrict__ Hout,
                                          int bg, int d, int layer,
                                          float* hbuf, float* ag) {
    constexpr int NJ = (CR == 0 || CR == 2) ? 52 : 48;
    constexpr int JB = (CR == 0) ? 0 : (CR == 1) ? 52 : (CR == 2) ? 100 : 152;
    constexpr int L0 = JB / 4;            // local ull2 range start
    constexpr int L1 = (JB + NJ) / 4;     // local ull2 range end
    const int tid = threadIdx.x;
    const int bb0 = bg * 2;
    const bool active = tid < 4 * NJ;
    const int gate = tid / NJ;
    const int jl = tid - gate * NJ;
    const int jglob = JB + jl;

    // U rows in registers: 100 packed k-pairs
    uint64_t upair[100];
    if (active) {
        const ulonglong2* Urow =
            (const ulonglong2*)(WhhD + (size_t)(gate * 200 + jglob) * 200);
#pragma unroll
        for (int kq = 0; kq < 50; kq++) {
            ulonglong2 t = Urow[kq];
            upair[2 * kq] = t.x;
            upair[2 * kq + 1] = t.y;
        }
    }
    for (int idx = tid; idx < 800; idx += 224) hbuf[idx] = 0.0f;
    __syncthreads();
    CL_ARRIVE(); CL_WAIT();   // all hbuf zeroed cluster-wide
    CL_ARRIVE();              // pre-loop arrive (paired by step-0 wait)

    const uint32_t hb_u32 = smem_u32(hbuf);
    float cst = 0.0f;
    int p = 0;

    for (int step = 0; step < 128; step++) {
        const int tstep = d ? (127 - step) : step;
        float gi0 = 0.f, gi1 = 0.f;
        uint64_t a00 = 0, a01 = 0, a10 = 0, a11 = 0;
        const ulonglong2* hp0 = (const ulonglong2*)(hbuf + (p * 2 + 0) * 200);
        const ulonglong2* hp1 = (const ulonglong2*)(hbuf + (p * 2 + 1) * 200);
        if (active) {
            const float* gb = GI + (size_t)(tstep * B + bb0) * NT + d * 800
                              + gate * 200 + jglob;
            gi0 = gb[0];
            gi1 = gb[NT];
            // local k-slice (own CTA's h, valid since last __syncthreads)
#pragma unroll
            for (int kq = L0; kq < L1; kq++) KQ_BODY(kq)
        }
        CL_WAIT();  // peers' h for this step now visible
        if (active) {
#pragma unroll
            for (int kq = 0; kq < L0; kq++) KQ_BODY(kq)
#pragma unroll
            for (int kq = L1; kq < 50; kq++) KQ_BODY(kq)
            float2 s00 = unpack2(a00), s01 = unpack2(a01);
            float2 s10 = unpack2(a10), s11 = unpack2(a11);
            ag[gate * (2 * NJ) + jl * 2 + 0] = (s00.x + s00.y) + (s01.x + s01.y) + gi0;
            ag[gate * (2 * NJ) + jl * 2 + 1] = (s10.x + s10.y) + (s11.x + s11.y) + gi1;
        }
        __syncthreads();
        // ---- phase B ----
        if (tid < 2 * NJ) {
            float aI = ag[0 * (2 * NJ) + tid];
            float aF = ag[1 * (2 * NJ) + tid];
            float aG = ag[2 * (2 * NJ) + tid];
            float aO = ag[3 * (2 * NJ) + tid];
            cst = fsig(aF) * cst + fsig(aI) * ftanh(aG);
            float hv = fsig(aO) * ftanh(cst);
            const int b = tid & 1, jlc = tid >> 1;
            const int jg = JB + jlc;
            const int pn = p ^ 1;
            const int off = (pn * 2 + b) * 200 + jg;
            hbuf[off] = hv;  // local, plain STS
            const uint32_t ha = hb_u32 + (uint32_t)(off * 4);
#pragma unroll
            for (int r = 0; r < 4; r++)
                if (r != CR) st_cluster_f32(ha, r, hv);
            float hstore = layer ? hv : __uint_as_float(f2tf32(hv));
            Hout[(size_t)(tstep * B + bb0 + b) * 400 + d * 200 + jg] = hstore;
        }
        __syncthreads();   // local h stores visible to whole CTA before next local loop
        CL_ARRIVE();       // release remote h stores; next step's wait pairs with it
        p ^= 1;
    }
    CL_WAIT();  // drain final arrive
}

__global__ void __cluster_dims__(4, 1, 1) __launch_bounds__(224, 1)
lstm_rec(const float* __restrict__ Whh, int layer) {
    const float* GI = layer ? g_GI1 : g_GI0;
    float* Hout     = layer ? g_H1  : g_H0;
    __shared__ __align__(16) float hbuf[2 * 2 * 200];
    __shared__ __align__(16) float ag[4 * 2 * 52];
    uint32_t crank;
    asm("mov.u32 %0, %%cluster_ctarank;" : "=r"(crank));
    const int bg = blockIdx.y >> 1;
    const int d  = blockIdx.y & 1;
    const float* WhhD = Whh + (size_t)d * (G * H);
    switch (crank) {
        case 0: lstm_body<0>(GI, WhhD, Hout, bg, d, layer, hbuf, ag); break;
        case 1: lstm_body<1>(GI, WhhD, Hout, bg, d, layer, hbuf, ag); break;
        case 2: lstm_body<2>(GI, WhhD, Hout, bg, d, layer, hbuf, ag); break;
        default: lstm_body<3>(GI, WhhD, Hout, bg, d, layer, hbuf, ag); break;
    }
}

// ---------------------------------------------------------------------------
// Output projection
// ---------------------------------------------------------------------------
__global__ void out_proj(const float* __restrict__ ow,
                         const float* __restrict__ ob, float* __restrict__ out) {
    __shared__ float x[400];
    const int m = blockIdx.x; // s*B + b
    const int tid = threadIdx.x;
    for (int i = tid; i < 400; i += blockDim.x) x[i] = g_H1[m * 400 + i];
    __syncthreads();
    if (tid < 136) {
        const int tt = tid >> 3, l = tid & 7;
        float acc = 0.0f;
        for (int k = l; k < 400; k += 8) acc = fmaf(x[k], ow[tt * 400 + k], acc);
        unsigned mask = (tid < 128) ? 0xffffffffu : 0xffu;
        acc += __shfl_down_sync(mask, acc, 4, 8);
        acc += __shfl_down_sync(mask, acc, 2, 8);
        acc += __shfl_down_sync(mask, acc, 1, 8);
        if (l == 0) {
            int s = m >> 5, b = m & 31;
            out[(b * S + s) * T + tt] = sigf(acc + ob[tt]);
        }
    }
}

// ---------------------------------------------------------------------------
extern "C" void kernel_launch(void* const* d_in, const int* in_sizes, int n_in,
                              void* d_out, int out_size) {
    const int* words = (const int*)d_in[0];
    const float* emb = (const float*)d_in[3];
    const float* Wih0 = (const float*)d_in[7];
    const float* Whh0 = (const float*)d_in[8];
    const float* b0 = (const float*)d_in[9];
    const float* Wih1 = (const float*)d_in[10];
    const float* Whh1 = (const float*)d_in[11];
    const float* b1 = (const float*)d_in[12];
    const float* ow = (const float*)d_in[13];
    const float* ob = (const float*)d_in[14];
    float* out = (float*)d_out;

    prep<<<dim3(2500, 3), 256>>>(Wih0, Wih1, words, emb);
    gemm_tc<<<dim3(NT / 64, MROWS / 128), 256>>>(b0, 300, 0);
    lstm_rec<<<dim3(4, 32), 224>>>(Whh0, 0);
    gemm_tc<<<dim3(NT / 64, MROWS / 128), 256>>>(b1, 400, 1);
    lstm_rec<<<dim3(4, 32), 224>>>(Whh1, 1);
    out_proj<<<MROWS, 160>>>(ow, ob, out);
}